// round 1
// baseline (speedup 1.0000x reference)
#include <cuda_runtime.h>
#include <math.h>

#define BB 8
#define EE 50000
#define DD 128
#define NN 10000

// ---------------- scratch (no allocations allowed) ----------------
__device__ float    g_dmean[BB*DD];   // per-batch per-feature sum (divide by E later)
__device__ unsigned g_gmax[BB];       // per-batch global max, float bits (ordered-uint trick)
__device__ int      g_hist[BB*NN];    // segment counts
__device__ int      g_off [BB*NN];    // exclusive prefix (segment start in perm)
__device__ int      g_cur [BB*NN];    // scatter cursors
__device__ int      g_perm[BB*EE];    // element ids sorted by segment

// ---------------- init ----------------
__global__ void k_init() {
    int i = blockIdx.x * blockDim.x + threadIdx.x;
    if (i < BB*NN) { g_hist[i] = 0; g_cur[i] = 0; }
    if (i < BB*DD) g_dmean[i] = 0.f;
    if (i < BB)    g_gmax[i] = 0xFF800000u;  // -inf
}

// ---------------- pass 1: per-batch global max + feature mean ----------------
// grid (ceil(E/512), B), block 512: col = tid&127, row-group = tid>>7
__global__ void k_stats(const float* __restrict__ data) {
    int b   = blockIdx.y;
    int col = threadIdx.x & (DD-1);
    int rg  = threadIdx.x >> 7;      // 0..3
    int r0  = blockIdx.x * 512;
    int r1  = min(r0 + 512, EE);
    float s = 0.f, m = -INFINITY;
    for (int e = r0 + rg; e < r1; e += 4) {
        float v = data[((size_t)b*EE + e)*DD + col];
        s += v;
        m = fmaxf(m, v);
    }
    __shared__ float sh[512];
    sh[threadIdx.x] = s;
    __syncthreads();
    if (rg == 0) {
        s = sh[col] + sh[col+128] + sh[col+256] + sh[col+384];
        atomicAdd(&g_dmean[b*DD + col], s);
    }
    // block max
    #pragma unroll
    for (int o = 16; o; o >>= 1) m = fmaxf(m, __shfl_xor_sync(0xffffffffu, m, o));
    __shared__ float wm[16];
    int wid = threadIdx.x >> 5, lane = threadIdx.x & 31;
    if (lane == 0) wm[wid] = m;
    __syncthreads();
    if (threadIdx.x == 0) {
        float mm = -INFINITY;
        #pragma unroll
        for (int i = 0; i < 16; i++) mm = fmaxf(mm, wm[i]);
        if (mm >= 0.f) atomicMax((int*)&g_gmax[b], __float_as_int(mm));
        else           atomicMin(&g_gmax[b], __float_as_uint(mm));
    }
}

// ---------------- counting sort: histogram ----------------
__global__ void k_hist(const int* __restrict__ idx) {
    int i = blockIdx.x * blockDim.x + threadIdx.x;
    if (i >= BB*EE) return;
    int b = i / EE;
    atomicAdd(&g_hist[b*NN + idx[i]], 1);
}

// ---------------- counting sort: per-batch exclusive scan (1 block/batch) ----------------
__global__ void k_scan() {
    __shared__ int sh[1024];
    const int CH = (NN + 1023) / 1024;   // 10
    int b = blockIdx.x, t = threadIdx.x;
    int lo = t * CH, hi = min(lo + CH, NN);
    int s = 0;
    for (int i = lo; i < hi; i++) s += g_hist[b*NN + i];
    sh[t] = s;
    __syncthreads();
    // Hillis-Steele inclusive scan
    for (int off = 1; off < 1024; off <<= 1) {
        int v = (t >= off) ? sh[t - off] : 0;
        __syncthreads();
        sh[t] += v;
        __syncthreads();
    }
    int run = (t == 0) ? 0 : sh[t - 1];
    for (int i = lo; i < hi; i++) {
        g_off[b*NN + i] = run;
        run += g_hist[b*NN + i];
    }
}

// ---------------- counting sort: scatter ----------------
__global__ void k_scatter(const int* __restrict__ idx) {
    int i = blockIdx.x * blockDim.x + threadIdx.x;
    if (i >= BB*EE) return;
    int b = i / EE, e = i - b*EE;
    int n = idx[i];
    int pos = g_off[b*NN + n] + atomicAdd(&g_cur[b*NN + n], 1);
    g_perm[b*EE + pos] = e;
}

// ---------------- main: one warp per segment, single pass ----------------
__global__ void __launch_bounds__(256) k_main(const float4* __restrict__ data,
                                              const float* __restrict__ betap,
                                              float* __restrict__ out) {
    int gw   = (blockIdx.x * blockDim.x + threadIdx.x) >> 5;
    int lane = threadIdx.x & 31;
    if (gw >= BB*NN) return;
    int b = gw / NN;
    int start = g_off[gw];
    int cnt   = g_hist[gw];

    float beta = *betap;
    float gmax = __uint_as_float(g_gmax[b]);
    const float invE = 1.f / (float)EE;
    float4 dm = reinterpret_cast<const float4*>(g_dmean)[b*32 + lane];
    dm.x *= invE; dm.y *= invE; dm.z *= invE; dm.w *= invE;

    float4 s  = make_float4(0.f,0.f,0.f,0.f);
    float4 mx = make_float4(-INFINITY,-INFINITY,-INFINITY,-INFINITY);
    float4 vr = make_float4(0.f,0.f,0.f,0.f);
    float4 dn = make_float4(0.f,0.f,0.f,0.f);
    float4 ws = make_float4(0.f,0.f,0.f,0.f);

    const float4* rb = data + (size_t)b * EE * (DD/4);
    const int* p = g_perm + b*EE + start;
    float bsh = -beta * gmax;   // exp(beta*v + bsh)

    for (int base = 0; base < cnt; base += 32) {
        int m = min(32, cnt - base);
        int e = (lane < m) ? p[base + lane] : 0;
        for (int k = 0; k < m; k++) {
            int ek = __shfl_sync(0xffffffffu, e, k);
            float4 v = __ldg(&rb[(size_t)ek * (DD/4) + lane]);
            s.x += v.x; s.y += v.y; s.z += v.z; s.w += v.w;
            mx.x = fmaxf(mx.x, v.x); mx.y = fmaxf(mx.y, v.y);
            mx.z = fmaxf(mx.z, v.z); mx.w = fmaxf(mx.w, v.w);
            float tx = v.x - dm.x, ty = v.y - dm.y, tz = v.z - dm.z, tw = v.w - dm.w;
            vr.x = fmaf(tx, tx, vr.x); vr.y = fmaf(ty, ty, vr.y);
            vr.z = fmaf(tz, tz, vr.z); vr.w = fmaf(tw, tw, vr.w);
            float nx = __expf(fmaf(beta, v.x, bsh));
            float ny = __expf(fmaf(beta, v.y, bsh));
            float nz = __expf(fmaf(beta, v.z, bsh));
            float nw = __expf(fmaf(beta, v.w, bsh));
            dn.x += nx; dn.y += ny; dn.z += nz; dn.w += nw;
            ws.x = fmaf(v.x, nx, ws.x); ws.y = fmaf(v.y, ny, ws.y);
            ws.z = fmaf(v.z, nz, ws.z); ws.w = fmaf(v.w, nw, ws.w);
        }
    }

    float inv = 1.f / ((cnt > 0) ? (float)cnt : 1.f);
    float4 mean = make_float4(s.x*inv, s.y*inv, s.z*inv, s.w*inv);
    float4 var  = make_float4(fmaxf(vr.x*inv,0.f), fmaxf(vr.y*inv,0.f),
                              fmaxf(vr.z*inv,0.f), fmaxf(vr.w*inv,0.f));
    if (cnt == 0) mx = make_float4(0.f,0.f,0.f,0.f);
    float4 soft;
    soft.x = ws.x / ((dn.x != 0.f) ? dn.x : 1.f);
    soft.y = ws.y / ((dn.y != 0.f) ? dn.y : 1.f);
    soft.z = ws.z / ((dn.z != 0.f) ? dn.z : 1.f);
    soft.w = ws.w / ((dn.w != 0.f) ? dn.w : 1.f);

    float4* ob = reinterpret_cast<float4*>(out + (size_t)gw * (5*DD));
    ob[lane]        = s;     // sum
    ob[32  + lane]  = mx;    // max
    ob[64  + lane]  = mean;  // mean
    ob[96  + lane]  = var;   // var
    ob[128 + lane]  = soft;  // softmax
}

// ---------------- launch ----------------
extern "C" void kernel_launch(void* const* d_in, const int* in_sizes, int n_in,
                              void* d_out, int out_size) {
    const float* data = nullptr;
    const float* beta = nullptr;
    const int*   idx  = nullptr;
    for (int i = 0; i < n_in; i++) {
        long long sz = in_sizes[i];
        if (sz == (long long)BB*EE*DD)      data = (const float*)d_in[i];
        else if (sz == (long long)BB*EE)    idx  = (const int*)d_in[i];
        else if (sz == 1 && beta == nullptr) beta = (const float*)d_in[i];
    }
    float* out = (float*)d_out;

    k_init<<<(BB*NN + 255)/256, 256>>>();
    dim3 gs((EE + 511)/512, BB);
    k_stats<<<gs, 512>>>(data);
    int nbe = (BB*EE + 255)/256;
    k_hist<<<nbe, 256>>>(idx);
    k_scan<<<BB, 1024>>>();
    k_scatter<<<nbe, 256>>>(idx);
    k_main<<<(BB*NN*32 + 255)/256, 256>>>((const float4*)data, beta, out);
}